// round 1
// baseline (speedup 1.0000x reference)
#include <cuda_runtime.h>

#define NB   2
#define NT   2048
#define ND   2048
#define NHQ  32
#define NHKV 8
#define NDH  64
#define NTOK (NB*NT)      // 4096
#define NDKV (NHKV*NDH)   // 512

// scratch (device globals: allocation-free per harness rules)
__device__ float g_Q[(size_t)NTOK * ND];    // 32 MB
__device__ float g_K[(size_t)NTOK * NDKV];  // 8 MB
__device__ float g_V[(size_t)NTOK * NDKV];  // 8 MB
__device__ float g_A[(size_t)NTOK * ND];    // 32 MB

// ---------------------------------------------------------------------------
// Classic 128x128x8 SGEMM, 256 threads, 8x8 register microtile.
// A [M,K] row-major, B [K,N] row-major, C [M,N] row-major. M%128==0, N%128==0, K%8==0.
// ---------------------------------------------------------------------------
__global__ __launch_bounds__(256) void sgemm128(
    const float* __restrict__ A, const float* __restrict__ B,
    float* __restrict__ C, int M, int N, int K)
{
    __shared__ float As[8][128];   // transposed A tile
    __shared__ float Bs[8][128];

    const int tid  = threadIdx.x;
    const int ty   = tid >> 4;         // 0..15
    const int tx   = tid & 15;         // 0..15
    const int arow = tid >> 1;         // 0..127
    const int acol = (tid & 1) * 4;    // 0 or 4
    const int brow = tid >> 5;         // 0..7
    const int bcol = (tid & 31) * 4;   // 0..124

    const float* Ab = A + (size_t)blockIdx.y * 128 * K;
    const float* Bb = B + (size_t)blockIdx.x * 128;

    float acc[8][8];
    #pragma unroll
    for (int i = 0; i < 8; i++)
        #pragma unroll
        for (int j = 0; j < 8; j++) acc[i][j] = 0.f;

    for (int k0 = 0; k0 < K; k0 += 8) {
        float4 a4 = *(const float4*)(Ab + (size_t)arow * K + k0 + acol);
        As[acol + 0][arow] = a4.x;
        As[acol + 1][arow] = a4.y;
        As[acol + 2][arow] = a4.z;
        As[acol + 3][arow] = a4.w;
        float4 b4 = *(const float4*)(Bb + (size_t)(k0 + brow) * N + bcol);
        *(float4*)&Bs[brow][bcol] = b4;
        __syncthreads();

        #pragma unroll
        for (int kk = 0; kk < 8; kk++) {
            float ar[8], br[8];
            *(float4*)&ar[0] = *(const float4*)&As[kk][ty * 8];
            *(float4*)&ar[4] = *(const float4*)&As[kk][ty * 8 + 4];
            *(float4*)&br[0] = *(const float4*)&Bs[kk][tx * 8];
            *(float4*)&br[4] = *(const float4*)&Bs[kk][tx * 8 + 4];
            #pragma unroll
            for (int i = 0; i < 8; i++)
                #pragma unroll
                for (int j = 0; j < 8; j++)
                    acc[i][j] += ar[i] * br[j];
        }
        __syncthreads();
    }

    float* Cb = C + (size_t)(blockIdx.y * 128 + ty * 8) * N + blockIdx.x * 128 + tx * 8;
    #pragma unroll
    for (int i = 0; i < 8; i++) {
        *(float4*)(Cb + (size_t)i * N)     = make_float4(acc[i][0], acc[i][1], acc[i][2], acc[i][3]);
        *(float4*)(Cb + (size_t)i * N + 4) = make_float4(acc[i][4], acc[i][5], acc[i][6], acc[i][7]);
    }
}

// ---------------------------------------------------------------------------
// Flash attention, non-causal. Br=Bc=64, dh=64. 256 threads.
// grid = (T/64, B*HQ). Q scratch [tok, D], K/V scratch [tok, HKV*64], out -> g_A.
// smem: sQ/sK/sV/sS each [64][65] (pad 65 -> conflict-free row reads), stats 3x64.
// ---------------------------------------------------------------------------
#define FA_SMEM ((4 * 64 * 65 + 3 * 64) * (int)sizeof(float))

__global__ __launch_bounds__(256) void flash_attn64(
    const float* __restrict__ Q, const float* __restrict__ K,
    const float* __restrict__ V, float* __restrict__ O)
{
    extern __shared__ float sm[];
    float* sQ = sm;               // 64*65
    float* sK = sQ + 64 * 65;
    float* sV = sK + 64 * 65;
    float* sS = sV + 64 * 65;
    float* sM = sS + 64 * 65;     // 64 row max
    float* sL = sM + 64;          // 64 row sum
    float* sA = sL + 64;          // 64 row rescale alpha

    const int tid = threadIdx.x;
    const int ty  = tid >> 4;     // 0..15
    const int tx  = tid & 15;     // 0..15
    const int bh  = blockIdx.y;
    const int b   = bh >> 5;      // / HQ
    const int h   = bh & 31;
    const int hkv = h >> 2;       // GQA group 4
    const int q0  = blockIdx.x * 64;
    const float scale = 0.125f;   // 1/sqrt(64)

    // load Q tile [64 x 64]: rows q0.., cols h*64..
    {
        const int r  = tid >> 2;
        const int c0 = (tid & 3) * 16;
        const float* src = Q + (size_t)(b * NT + q0 + r) * ND + h * NDH + c0;
        #pragma unroll
        for (int i = 0; i < 4; i++) {
            float4 v = *(const float4*)(src + i * 4);
            float* d = &sQ[r * 65 + c0 + i * 4];
            d[0] = v.x; d[1] = v.y; d[2] = v.z; d[3] = v.w;
        }
    }
    if (tid < 64) { sM[tid] = -1e30f; sL[tid] = 0.f; }

    float o[4][4];
    #pragma unroll
    for (int i = 0; i < 4; i++)
        #pragma unroll
        for (int j = 0; j < 4; j++) o[i][j] = 0.f;

    for (int kb = 0; kb < NT / 64; kb++) {
        __syncthreads();   // prior iter done with sK/sV/sS
        // load K/V tiles [64 x 64]
        {
            const int r  = tid >> 2;
            const int c0 = (tid & 3) * 16;
            const float* ks = K + (size_t)(b * NT + kb * 64 + r) * NDKV + hkv * NDH + c0;
            const float* vs = V + (size_t)(b * NT + kb * 64 + r) * NDKV + hkv * NDH + c0;
            #pragma unroll
            for (int i = 0; i < 4; i++) {
                float4 kv = *(const float4*)(ks + i * 4);
                float* dk = &sK[r * 65 + c0 + i * 4];
                dk[0] = kv.x; dk[1] = kv.y; dk[2] = kv.z; dk[3] = kv.w;
                float4 vv = *(const float4*)(vs + i * 4);
                float* dv = &sV[r * 65 + c0 + i * 4];
                dv[0] = vv.x; dv[1] = vv.y; dv[2] = vv.z; dv[3] = vv.w;
            }
        }
        __syncthreads();

        // phase A: S[64][64] = scale * Q K^T  (4x4 microtile per thread)
        {
            float acc[4][4];
            #pragma unroll
            for (int i = 0; i < 4; i++)
                #pragma unroll
                for (int j = 0; j < 4; j++) acc[i][j] = 0.f;
            #pragma unroll 4
            for (int d = 0; d < 64; d++) {
                float aq[4], bk[4];
                #pragma unroll
                for (int i = 0; i < 4; i++) aq[i] = sQ[(ty * 4 + i) * 65 + d];
                #pragma unroll
                for (int j = 0; j < 4; j++) bk[j] = sK[(tx * 4 + j) * 65 + d];
                #pragma unroll
                for (int i = 0; i < 4; i++)
                    #pragma unroll
                    for (int j = 0; j < 4; j++)
                        acc[i][j] += aq[i] * bk[j];
            }
            #pragma unroll
            for (int i = 0; i < 4; i++)
                #pragma unroll
                for (int j = 0; j < 4; j++)
                    sS[(ty * 4 + i) * 65 + tx * 4 + j] = acc[i][j] * scale;
        }
        __syncthreads();

        // phase B: online softmax per row (64 threads, one row each)
        if (tid < 64) {
            float mo = sM[tid];
            float mn = mo;
            float* row = &sS[tid * 65];
            #pragma unroll
            for (int j = 0; j < 64; j++) mn = fmaxf(mn, row[j]);
            float al = __expf(mo - mn);
            float l  = sL[tid] * al;
            #pragma unroll
            for (int j = 0; j < 64; j++) {
                float p = __expf(row[j] - mn);
                row[j] = p;
                l += p;
            }
            sM[tid] = mn; sL[tid] = l; sA[tid] = al;
        }
        __syncthreads();

        // phase C: O = O*alpha + P @ V
        {
            float al[4];
            #pragma unroll
            for (int i = 0; i < 4; i++) al[i] = sA[ty * 4 + i];
            #pragma unroll
            for (int i = 0; i < 4; i++)
                #pragma unroll
                for (int j = 0; j < 4; j++) o[i][j] *= al[i];
            #pragma unroll 4
            for (int jk = 0; jk < 64; jk++) {
                float ap[4], bv[4];
                #pragma unroll
                for (int i = 0; i < 4; i++) ap[i] = sS[(ty * 4 + i) * 65 + jk];
                #pragma unroll
                for (int c = 0; c < 4; c++) bv[c] = sV[jk * 65 + tx * 4 + c];
                #pragma unroll
                for (int i = 0; i < 4; i++)
                    #pragma unroll
                    for (int c = 0; c < 4; c++)
                        o[i][c] += ap[i] * bv[c];
            }
        }
    }
    __syncthreads();

    // normalize + write [b, q, h*64+c]
    #pragma unroll
    for (int i = 0; i < 4; i++) {
        const int r = ty * 4 + i;
        const float inv = 1.0f / sL[r];
        float4 v = make_float4(o[i][0] * inv, o[i][1] * inv, o[i][2] * inv, o[i][3] * inv);
        *(float4*)(O + (size_t)(b * NT + q0 + r) * ND + h * NDH + tx * 4) = v;
    }
}

// ---------------------------------------------------------------------------
extern "C" void kernel_launch(void* const* d_in, const int* in_sizes, int n_in,
                              void* d_out, int out_size)
{
    const float* x  = (const float*)d_in[0];
    const float* Wq = (const float*)d_in[1];
    const float* Wk = (const float*)d_in[2];
    const float* Wv = (const float*)d_in[3];
    const float* Wo = (const float*)d_in[4];
    float* out = (float*)d_out;

    float *Qp, *Kp, *Vp, *Ap;
    cudaGetSymbolAddress((void**)&Qp, g_Q);
    cudaGetSymbolAddress((void**)&Kp, g_K);
    cudaGetSymbolAddress((void**)&Vp, g_V);
    cudaGetSymbolAddress((void**)&Ap, g_A);

    cudaFuncSetAttribute(flash_attn64,
                         cudaFuncAttributeMaxDynamicSharedMemorySize, FA_SMEM);

    dim3 gq(ND / 128, NTOK / 128);     // (16, 32)
    dim3 gkv(NDKV / 128, NTOK / 128);  // (4, 32)

    sgemm128<<<gq, 256>>>(x, Wq, Qp, NTOK, ND, ND);
    sgemm128<<<gkv, 256>>>(x, Wk, Kp, NTOK, NDKV, ND);
    sgemm128<<<gkv, 256>>>(x, Wv, Vp, NTOK, NDKV, ND);

    flash_attn64<<<dim3(NT / 64, NB * NHQ), 256, FA_SMEM>>>(Qp, Kp, Vp, Ap);

    sgemm128<<<gq, 256>>>(Ap, Wo, out, NTOK, ND, ND);
}

// round 2
// speedup vs baseline: 1.4432x; 1.4432x over previous
#include <cuda_runtime.h>
#include <cstdint>

#define NB   2
#define NT   2048
#define ND   2048
#define NHQ  32
#define NHKV 8
#define NDH  64
#define NTOK (NB*NT)      // 4096
#define NDKV (NHKV*NDH)   // 512

// scratch (device globals: allocation-free per harness rules)
__device__ float g_Q[(size_t)NTOK * ND];    // 32 MB
__device__ float g_K[(size_t)NTOK * NDKV];  // 8 MB
__device__ float g_V[(size_t)NTOK * NDKV];  // 8 MB
__device__ float g_A[(size_t)NTOK * ND];    // 32 MB

// ---------------------------------------------------------------------------
// tf32 helpers
// ---------------------------------------------------------------------------
__device__ __forceinline__ float to_tf32(float x) {
    float r;
    asm("cvt.rna.tf32.f32 %0, %1;" : "=f"(r) : "f"(x));
    return r;
}

__device__ __forceinline__ void mma_tf32(float* c, uint32_t a0, uint32_t a1,
                                         uint32_t a2, uint32_t a3,
                                         uint32_t b0, uint32_t b1) {
    asm volatile(
        "mma.sync.aligned.m16n8k8.row.col.f32.tf32.tf32.f32 "
        "{%0,%1,%2,%3}, {%4,%5,%6,%7}, {%8,%9}, {%0,%1,%2,%3};"
        : "+f"(c[0]), "+f"(c[1]), "+f"(c[2]), "+f"(c[3])
        : "r"(a0), "r"(a1), "r"(a2), "r"(a3), "r"(b0), "r"(b1));
}

// ---------------------------------------------------------------------------
// tf32 tensor-core GEMM: C[M,N] = A[M,K] @ B[K,N], all row-major fp32 in/out.
// 128x128 tile, BK=16, 256 threads = 8 warps (2x4). Warp tile 64x32 via
// m16n8k8 (4 m-frags x 4 n-frags). M%128==0, N%128==0, K%16==0.
// smem stride 136 floats -> fragment gathers are bank-conflict-free (g + 8t).
// ---------------------------------------------------------------------------
__global__ __launch_bounds__(256) void gemm_tf32(
    const float* __restrict__ A, const float* __restrict__ B,
    float* __restrict__ C, int M, int N, int K)
{
    __shared__ float As[16][136];   // [k][m]
    __shared__ float Bs[16][136];   // [k][n]

    const int tid  = threadIdx.x;
    const int warp = tid >> 5;
    const int lane = tid & 31;
    const int g    = lane >> 2;     // 0..7
    const int t    = lane & 3;      // 0..3
    const int wm   = warp >> 2;     // 0..1
    const int wn   = warp & 3;      // 0..3
    const int mbase = wm * 64;
    const int nbase = wn * 32;

    const int ar = tid >> 1;            // 0..127
    const int ac = (tid & 1) * 8;       // 0 or 8
    const int br = tid >> 4;            // 0..15
    const int bc = (tid & 15) * 8;      // 0..120

    const float* Ab = A + (size_t)(blockIdx.y * 128 + ar) * K + ac;
    const float* Bb = B + (size_t)br * N + blockIdx.x * 128 + bc;

    float acc[4][4][4];
    #pragma unroll
    for (int i = 0; i < 4; i++)
        #pragma unroll
        for (int j = 0; j < 4; j++)
            #pragma unroll
            for (int r = 0; r < 4; r++) acc[i][j][r] = 0.f;

    for (int k0 = 0; k0 < K; k0 += 16) {
        // stage A tile (transposed) with tf32 rounding
        {
            float4 v0 = *(const float4*)(Ab + k0);
            float4 v1 = *(const float4*)(Ab + k0 + 4);
            As[ac + 0][ar] = to_tf32(v0.x);
            As[ac + 1][ar] = to_tf32(v0.y);
            As[ac + 2][ar] = to_tf32(v0.z);
            As[ac + 3][ar] = to_tf32(v0.w);
            As[ac + 4][ar] = to_tf32(v1.x);
            As[ac + 5][ar] = to_tf32(v1.y);
            As[ac + 6][ar] = to_tf32(v1.z);
            As[ac + 7][ar] = to_tf32(v1.w);
        }
        // stage B tile
        {
            const float* bp = Bb + (size_t)k0 * N;
            float4 w0 = *(const float4*)(bp);
            float4 w1 = *(const float4*)(bp + 4);
            float* d = &Bs[br][bc];
            d[0] = to_tf32(w0.x); d[1] = to_tf32(w0.y);
            d[2] = to_tf32(w0.z); d[3] = to_tf32(w0.w);
            d[4] = to_tf32(w1.x); d[5] = to_tf32(w1.y);
            d[6] = to_tf32(w1.z); d[7] = to_tf32(w1.w);
        }
        __syncthreads();

        #pragma unroll
        for (int ks = 0; ks < 16; ks += 8) {
            uint32_t af[4][4];
            #pragma unroll
            for (int mf = 0; mf < 4; mf++) {
                const int m0 = mbase + mf * 16 + g;
                af[mf][0] = __float_as_uint(As[ks + t    ][m0]);
                af[mf][1] = __float_as_uint(As[ks + t    ][m0 + 8]);
                af[mf][2] = __float_as_uint(As[ks + t + 4][m0]);
                af[mf][3] = __float_as_uint(As[ks + t + 4][m0 + 8]);
            }
            uint32_t bf[4][2];
            #pragma unroll
            for (int nf = 0; nf < 4; nf++) {
                const int n0 = nbase + nf * 8 + g;
                bf[nf][0] = __float_as_uint(Bs[ks + t    ][n0]);
                bf[nf][1] = __float_as_uint(Bs[ks + t + 4][n0]);
            }
            #pragma unroll
            for (int mf = 0; mf < 4; mf++)
                #pragma unroll
                for (int nf = 0; nf < 4; nf++)
                    mma_tf32(acc[mf][nf], af[mf][0], af[mf][1], af[mf][2],
                             af[mf][3], bf[nf][0], bf[nf][1]);
        }
        __syncthreads();
    }

    // epilogue: c0/c1 at (row, 2t/2t+1), c2/c3 at (row+8, ...)
    #pragma unroll
    for (int mf = 0; mf < 4; mf++) {
        const int row = blockIdx.y * 128 + mbase + mf * 16 + g;
        #pragma unroll
        for (int nf = 0; nf < 4; nf++) {
            const int col = blockIdx.x * 128 + nbase + nf * 8 + 2 * t;
            *(float2*)(C + (size_t)row * N + col) =
                make_float2(acc[mf][nf][0], acc[mf][nf][1]);
            *(float2*)(C + (size_t)(row + 8) * N + col) =
                make_float2(acc[mf][nf][2], acc[mf][nf][3]);
        }
    }
}

// ---------------------------------------------------------------------------
// Flash attention, non-causal. Br=Bc=64, dh=64. 256 threads.
// grid = (T/64, B*HQ). smem padded to 65 floats/row (conflict-free).
// ---------------------------------------------------------------------------
#define FA_SMEM ((4 * 64 * 65 + 3 * 64) * (int)sizeof(float))

__global__ __launch_bounds__(256) void flash_attn64(
    const float* __restrict__ Q, const float* __restrict__ K,
    const float* __restrict__ V, float* __restrict__ O)
{
    extern __shared__ float sm[];
    float* sQ = sm;               // 64*65
    float* sK = sQ + 64 * 65;
    float* sV = sK + 64 * 65;
    float* sS = sV + 64 * 65;
    float* sM = sS + 64 * 65;     // 64 row max
    float* sL = sM + 64;          // 64 row sum
    float* sA = sL + 64;          // 64 row rescale alpha

    const int tid = threadIdx.x;
    const int ty  = tid >> 4;     // 0..15
    const int tx  = tid & 15;     // 0..15
    const int bh  = blockIdx.y;
    const int b   = bh >> 5;      // / HQ
    const int h   = bh & 31;
    const int hkv = h >> 2;       // GQA group 4
    const int q0  = blockIdx.x * 64;
    const float scale = 0.125f;   // 1/sqrt(64)

    // load Q tile [64 x 64]
    {
        const int r  = tid >> 2;
        const int c0 = (tid & 3) * 16;
        const float* src = Q + (size_t)(b * NT + q0 + r) * ND + h * NDH + c0;
        #pragma unroll
        for (int i = 0; i < 4; i++) {
            float4 v = *(const float4*)(src + i * 4);
            float* d = &sQ[r * 65 + c0 + i * 4];
            d[0] = v.x; d[1] = v.y; d[2] = v.z; d[3] = v.w;
        }
    }
    if (tid < 64) { sM[tid] = -1e30f; sL[tid] = 0.f; }

    float o[4][4];
    #pragma unroll
    for (int i = 0; i < 4; i++)
        #pragma unroll
        for (int j = 0; j < 4; j++) o[i][j] = 0.f;

    for (int kb = 0; kb < NT / 64; kb++) {
        __syncthreads();
        // load K/V tiles [64 x 64]
        {
            const int r  = tid >> 2;
            const int c0 = (tid & 3) * 16;
            const float* ks = K + (size_t)(b * NT + kb * 64 + r) * NDKV + hkv * NDH + c0;
            const float* vs = V + (size_t)(b * NT + kb * 64 + r) * NDKV + hkv * NDH + c0;
            #pragma unroll
            for (int i = 0; i < 4; i++) {
                float4 kv = *(const float4*)(ks + i * 4);
                float* dk = &sK[r * 65 + c0 + i * 4];
                dk[0] = kv.x; dk[1] = kv.y; dk[2] = kv.z; dk[3] = kv.w;
                float4 vv = *(const float4*)(vs + i * 4);
                float* dv = &sV[r * 65 + c0 + i * 4];
                dv[0] = vv.x; dv[1] = vv.y; dv[2] = vv.z; dv[3] = vv.w;
            }
        }
        __syncthreads();

        // phase A: S = scale * Q K^T
        {
            float acc[4][4];
            #pragma unroll
            for (int i = 0; i < 4; i++)
                #pragma unroll
                for (int j = 0; j < 4; j++) acc[i][j] = 0.f;
            #pragma unroll 4
            for (int d = 0; d < 64; d++) {
                float aq[4], bk[4];
                #pragma unroll
                for (int i = 0; i < 4; i++) aq[i] = sQ[(ty * 4 + i) * 65 + d];
                #pragma unroll
                for (int j = 0; j < 4; j++) bk[j] = sK[(tx * 4 + j) * 65 + d];
                #pragma unroll
                for (int i = 0; i < 4; i++)
                    #pragma unroll
                    for (int j = 0; j < 4; j++)
                        acc[i][j] += aq[i] * bk[j];
            }
            #pragma unroll
            for (int i = 0; i < 4; i++)
                #pragma unroll
                for (int j = 0; j < 4; j++)
                    sS[(ty * 4 + i) * 65 + tx * 4 + j] = acc[i][j] * scale;
        }
        __syncthreads();

        // phase B: online softmax, 4 lanes per row (256 threads)
        {
            const int r  = tid >> 2;     // row 0..63
            const int t4 = tid & 3;
            float* row = &sS[r * 65 + t4 * 16];
            float mloc = -1e30f;
            #pragma unroll
            for (int j = 0; j < 16; j++) mloc = fmaxf(mloc, row[j]);
            mloc = fmaxf(mloc, __shfl_xor_sync(0xffffffffu, mloc, 1));
            mloc = fmaxf(mloc, __shfl_xor_sync(0xffffffffu, mloc, 2));
            const float mo = sM[r];
            const float mn = fmaxf(mo, mloc);
            float l = 0.f;
            #pragma unroll
            for (int j = 0; j < 16; j++) {
                float p = __expf(row[j] - mn);
                row[j] = p;
                l += p;
            }
            l += __shfl_xor_sync(0xffffffffu, l, 1);
            l += __shfl_xor_sync(0xffffffffu, l, 2);
            if (t4 == 0) {
                const float al = __expf(mo - mn);
                sA[r] = al;
                sM[r] = mn;
                sL[r] = sL[r] * al + l;
            }
        }
        __syncthreads();

        // phase C: O = O*alpha + P @ V
        {
            float al[4];
            #pragma unroll
            for (int i = 0; i < 4; i++) al[i] = sA[ty * 4 + i];
            #pragma unroll
            for (int i = 0; i < 4; i++)
                #pragma unroll
                for (int j = 0; j < 4; j++) o[i][j] *= al[i];
            #pragma unroll 4
            for (int jk = 0; jk < 64; jk++) {
                float ap[4], bv[4];
                #pragma unroll
                for (int i = 0; i < 4; i++) ap[i] = sS[(ty * 4 + i) * 65 + jk];
                #pragma unroll
                for (int c = 0; c < 4; c++) bv[c] = sV[jk * 65 + tx * 4 + c];
                #pragma unroll
                for (int i = 0; i < 4; i++)
                    #pragma unroll
                    for (int c = 0; c < 4; c++)
                        o[i][c] += ap[i] * bv[c];
            }
        }
    }
    __syncthreads();

    // normalize + write
    #pragma unroll
    for (int i = 0; i < 4; i++) {
        const int r = ty * 4 + i;
        const float inv = 1.0f / sL[r];
        float4 v = make_float4(o[i][0] * inv, o[i][1] * inv, o[i][2] * inv, o[i][3] * inv);
        *(float4*)(O + (size_t)(b * NT + q0 + r) * ND + h * NDH + tx * 4) = v;
    }
}

// ---------------------------------------------------------------------------
extern "C" void kernel_launch(void* const* d_in, const int* in_sizes, int n_in,
                              void* d_out, int out_size)
{
    const float* x  = (const float*)d_in[0];
    const float* Wq = (const float*)d_in[1];
    const float* Wk = (const float*)d_in[2];
    const float* Wv = (const float*)d_in[3];
    const float* Wo = (const float*)d_in[4];
    float* out = (float*)d_out;

    float *Qp, *Kp, *Vp, *Ap;
    cudaGetSymbolAddress((void**)&Qp, g_Q);
    cudaGetSymbolAddress((void**)&Kp, g_K);
    cudaGetSymbolAddress((void**)&Vp, g_V);
    cudaGetSymbolAddress((void**)&Ap, g_A);

    cudaFuncSetAttribute(flash_attn64,
                         cudaFuncAttributeMaxDynamicSharedMemorySize, FA_SMEM);

    dim3 gq(ND / 128, NTOK / 128);     // (16, 32)
    dim3 gkv(NDKV / 128, NTOK / 128);  // (4, 32)

    gemm_tf32<<<gq, 256>>>(x, Wq, Qp, NTOK, ND, ND);
    gemm_tf32<<<gkv, 256>>>(x, Wk, Kp, NTOK, NDKV, ND);
    gemm_tf32<<<gkv, 256>>>(x, Wv, Vp, NTOK, NDKV, ND);

    flash_attn64<<<dim3(NT / 64, NB * NHQ), 256, FA_SMEM>>>(Qp, Kp, Vp, Ap);

    gemm_tf32<<<gq, 256>>>(Ap, Wo, out, NTOK, ND, ND);
}

// round 4
// speedup vs baseline: 2.8254x; 1.9578x over previous
#include <cuda_runtime.h>
#include <cstdint>

#define NB   2
#define NT   2048
#define ND   2048
#define NHQ  32
#define NHKV 8
#define NDH  64
#define NTOK (NB*NT)      // 4096
#define NDKV (NHKV*NDH)   // 512

// scratch (device globals: allocation-free per harness rules)
__device__ float g_Q[(size_t)NTOK * ND];    // 32 MB
__device__ float g_K[(size_t)NTOK * NDKV];  // 8 MB
__device__ float g_V[(size_t)NTOK * NDKV];  // 8 MB
__device__ float g_A[(size_t)NTOK * ND];    // 32 MB

// ---------------------------------------------------------------------------
// tf32 helpers
// ---------------------------------------------------------------------------
__device__ __forceinline__ float to_tf32(float x) {
    float r;
    asm("cvt.rna.tf32.f32 %0, %1;" : "=f"(r) : "f"(x));
    return r;
}

__device__ __forceinline__ void mma_tf32(float* c, uint32_t a0, uint32_t a1,
                                         uint32_t a2, uint32_t a3,
                                         uint32_t b0, uint32_t b1) {
    asm volatile(
        "mma.sync.aligned.m16n8k8.row.col.f32.tf32.tf32.f32 "
        "{%0,%1,%2,%3}, {%4,%5,%6,%7}, {%8,%9}, {%0,%1,%2,%3};"
        : "+f"(c[0]), "+f"(c[1]), "+f"(c[2]), "+f"(c[3])
        : "r"(a0), "r"(a1), "r"(a2), "r"(a3), "r"(b0), "r"(b1));
}

__device__ __forceinline__ void cp_async16(void* smem_ptr, const void* gptr) {
    unsigned saddr = (unsigned)__cvta_generic_to_shared(smem_ptr);
    asm volatile("cp.async.cg.shared.global [%0], [%1], 16;\n"
                 :: "r"(saddr), "l"(gptr));
}

// ---------------------------------------------------------------------------
// tf32 tensor-core GEMM: C[M,N] = A[M,K] @ B[K,N], row-major fp32.
// ---------------------------------------------------------------------------
__global__ __launch_bounds__(256) void gemm_tf32(
    const float* __restrict__ A, const float* __restrict__ B,
    float* __restrict__ C, int M, int N, int K)
{
    __shared__ float As[16][136];   // [k][m]
    __shared__ float Bs[16][136];   // [k][n]

    const int tid  = threadIdx.x;
    const int warp = tid >> 5;
    const int lane = tid & 31;
    const int g    = lane >> 2;
    const int t    = lane & 3;
    const int wm   = warp >> 2;
    const int wn   = warp & 3;
    const int mbase = wm * 64;
    const int nbase = wn * 32;

    const int ar = tid >> 1;
    const int ac = (tid & 1) * 8;
    const int br = tid >> 4;
    const int bc = (tid & 15) * 8;

    const float* Ab = A + (size_t)(blockIdx.y * 128 + ar) * K + ac;
    const float* Bb = B + (size_t)br * N + blockIdx.x * 128 + bc;

    float acc[4][4][4];
    #pragma unroll
    for (int i = 0; i < 4; i++)
        #pragma unroll
        for (int j = 0; j < 4; j++)
            #pragma unroll
            for (int r = 0; r < 4; r++) acc[i][j][r] = 0.f;

    for (int k0 = 0; k0 < K; k0 += 16) {
        {
            float4 v0 = *(const float4*)(Ab + k0);
            float4 v1 = *(const float4*)(Ab + k0 + 4);
            As[ac + 0][ar] = to_tf32(v0.x);
            As[ac + 1][ar] = to_tf32(v0.y);
            As[ac + 2][ar] = to_tf32(v0.z);
            As[ac + 3][ar] = to_tf32(v0.w);
            As[ac + 4][ar] = to_tf32(v1.x);
            As[ac + 5][ar] = to_tf32(v1.y);
            As[ac + 6][ar] = to_tf32(v1.z);
            As[ac + 7][ar] = to_tf32(v1.w);
        }
        {
            const float* bp = Bb + (size_t)k0 * N;
            float4 w0 = *(const float4*)(bp);
            float4 w1 = *(const float4*)(bp + 4);
            float* d = &Bs[br][bc];
            d[0] = to_tf32(w0.x); d[1] = to_tf32(w0.y);
            d[2] = to_tf32(w0.z); d[3] = to_tf32(w0.w);
            d[4] = to_tf32(w1.x); d[5] = to_tf32(w1.y);
            d[6] = to_tf32(w1.z); d[7] = to_tf32(w1.w);
        }
        __syncthreads();

        #pragma unroll
        for (int ks = 0; ks < 16; ks += 8) {
            uint32_t af[4][4];
            #pragma unroll
            for (int mf = 0; mf < 4; mf++) {
                const int m0 = mbase + mf * 16 + g;
                af[mf][0] = __float_as_uint(As[ks + t    ][m0]);
                af[mf][1] = __float_as_uint(As[ks + t    ][m0 + 8]);
                af[mf][2] = __float_as_uint(As[ks + t + 4][m0]);
                af[mf][3] = __float_as_uint(As[ks + t + 4][m0 + 8]);
            }
            uint32_t bf[4][2];
            #pragma unroll
            for (int nf = 0; nf < 4; nf++) {
                const int n0 = nbase + nf * 8 + g;
                bf[nf][0] = __float_as_uint(Bs[ks + t    ][n0]);
                bf[nf][1] = __float_as_uint(Bs[ks + t + 4][n0]);
            }
            #pragma unroll
            for (int mf = 0; mf < 4; mf++)
                #pragma unroll
                for (int nf = 0; nf < 4; nf++)
                    mma_tf32(acc[mf][nf], af[mf][0], af[mf][1], af[mf][2],
                             af[mf][3], bf[nf][0], bf[nf][1]);
        }
        __syncthreads();
    }

    #pragma unroll
    for (int mf = 0; mf < 4; mf++) {
        const int row = blockIdx.y * 128 + mbase + mf * 16 + g;
        #pragma unroll
        for (int nf = 0; nf < 4; nf++) {
            const int col = blockIdx.x * 128 + nbase + nf * 8 + 2 * t;
            *(float2*)(C + (size_t)row * N + col) =
                make_float2(acc[mf][nf][0], acc[mf][nf][1]);
            *(float2*)(C + (size_t)(row + 8) * N + col) =
                make_float2(acc[mf][nf][2], acc[mf][nf][3]);
        }
    }
}

// ---------------------------------------------------------------------------
// MMA flash attention (tf32). Br=128 (8 warps x 16 rows), Bc=64, dh=64.
// Q in registers for the whole loop; softmax in registers (quad shuffles);
// K double-buffered via cp.async; V double-buffered via LDG+transposed STS.
// smem pitch 68 floats -> fragment gathers conflict-free.
// ---------------------------------------------------------------------------
#define FA_P 68
#define FA2_SMEM (4 * 64 * FA_P * (int)sizeof(float))   // 69632 B

__global__ __launch_bounds__(256) void flash_mma(
    const float* __restrict__ Q, const float* __restrict__ K,
    const float* __restrict__ V, float* __restrict__ O)
{
    extern __shared__ float sm[];
    float* sKb[2]  = { sm,                sm + 2 * 64 * FA_P };
    float* sVt[2]  = { sm + 64 * FA_P,    sm + 3 * 64 * FA_P };
    float* Qs      = sm + 2 * 64 * FA_P;  // 128 x 68, aliases buffers 2+3

    const int tid  = threadIdx.x;
    const int warp = tid >> 5;
    const int lane = tid & 31;
    const int g    = lane >> 2;      // 0..7
    const int tq   = lane & 3;       // 0..3
    const int bh   = blockIdx.y;
    const int b    = bh >> 5;
    const int h    = bh & 31;
    const int hkv  = h >> 2;
    const int q0   = blockIdx.x * 128;

    const int krow = tid >> 2;          // 0..63
    const int kcol = (tid & 3) * 16;    // 0,16,32,48

    // --- prologue: cp.async K tile 0 (full 16 floats per thread) ---
    {
        const float* src = K + (size_t)(b * NT + krow) * NDKV + hkv * NDH + kcol;
        #pragma unroll
        for (int i = 0; i < 4; i++)
            cp_async16(&sKb[0][krow * FA_P + kcol + 4 * i], src + 4 * i);
        asm volatile("cp.async.commit_group;\n" ::: "memory");
    }
    // --- V tile 0: LDG into registers ---
    const int vrow = tid & 63;
    const int vcb  = (tid >> 6) * 16;
    float4 vr[4];
    {
        const float* src = V + (size_t)(b * NT + vrow) * NDKV + hkv * NDH + vcb;
        #pragma unroll
        for (int i = 0; i < 4; i++) vr[i] = *(const float4*)(src + 4 * i);
    }
    // --- stage Q (scaled, tf32-rounded) ---
    {
        const int r  = tid >> 1;
        const int c0 = (tid & 1) * 32;
        const float* src = Q + (size_t)(b * NT + q0 + r) * ND + h * NDH + c0;
        #pragma unroll
        for (int i = 0; i < 8; i++) {
            float4 v = *(const float4*)(src + 4 * i);
            float* d = &Qs[r * FA_P + c0 + 4 * i];
            d[0] = to_tf32(0.125f * v.x);
            d[1] = to_tf32(0.125f * v.y);
            d[2] = to_tf32(0.125f * v.z);
            d[3] = to_tf32(0.125f * v.w);
        }
    }
    __syncthreads();

    // --- Q fragments into registers (held for entire KV loop) ---
    uint32_t qa[8][4];
    {
        const float* qr0 = &Qs[(warp * 16 + g) * FA_P];
        const float* qr1 = qr0 + 8 * FA_P;
        #pragma unroll
        for (int ks = 0; ks < 8; ks++) {
            qa[ks][0] = __float_as_uint(qr0[8 * ks + tq]);
            qa[ks][1] = __float_as_uint(qr1[8 * ks + tq]);
            qa[ks][2] = __float_as_uint(qr0[8 * ks + tq + 4]);
            qa[ks][3] = __float_as_uint(qr1[8 * ks + tq + 4]);
        }
    }
    // --- STS V tile 0 (transposed) ---
    {
        float* dst = sVt[0];
        #pragma unroll
        for (int i = 0; i < 4; i++) {
            dst[(vcb + 4 * i + 0) * FA_P + vrow] = to_tf32(vr[i].x);
            dst[(vcb + 4 * i + 1) * FA_P + vrow] = to_tf32(vr[i].y);
            dst[(vcb + 4 * i + 2) * FA_P + vrow] = to_tf32(vr[i].z);
            dst[(vcb + 4 * i + 3) * FA_P + vrow] = to_tf32(vr[i].w);
        }
    }
    __syncthreads();   // Q frag reads done; sVt0 ready

    float m0 = -1e30f, m1 = -1e30f, l0 = 0.f, l1 = 0.f;
    float acc_o[8][4];
    #pragma unroll
    for (int j = 0; j < 8; j++)
        #pragma unroll
        for (int r = 0; r < 4; r++) acc_o[j][r] = 0.f;

    const unsigned fm   = 0xffffffffu;
    const int      src0 = (lane & 28) | (tq >> 1);
    const int      src2 = src0 + 2;

    for (int kb = 0; kb < NT / 64; kb++) {
        const int buf = kb & 1;
        asm volatile("cp.async.wait_group 0;\n" ::: "memory");
        __syncthreads();

        const bool pre = (kb + 1 < NT / 64);
        if (pre) {
            const float* src = K + (size_t)(b * NT + (kb + 1) * 64 + krow) * NDKV
                               + hkv * NDH + kcol;
            #pragma unroll
            for (int i = 0; i < 4; i++)
                cp_async16(&sKb[buf ^ 1][krow * FA_P + kcol + 4 * i], src + 4 * i);
            asm volatile("cp.async.commit_group;\n" ::: "memory");
            const float* vsrc = V + (size_t)(b * NT + (kb + 1) * 64 + vrow) * NDKV
                                + hkv * NDH + vcb;
            #pragma unroll
            for (int i = 0; i < 4; i++) vr[i] = *(const float4*)(vsrc + 4 * i);
        }

        // --- QK^T ---
        float s[8][4];
        #pragma unroll
        for (int j = 0; j < 8; j++)
            #pragma unroll
            for (int r = 0; r < 4; r++) s[j][r] = 0.f;
        {
            const float* kp = sKb[buf];
            #pragma unroll
            for (int ks = 0; ks < 8; ks++) {
                #pragma unroll
                for (int j = 0; j < 8; j++) {
                    const float b0 = kp[(8 * j + g) * FA_P + 8 * ks + tq];
                    const float b1 = kp[(8 * j + g) * FA_P + 8 * ks + tq + 4];
                    mma_tf32(s[j], qa[ks][0], qa[ks][1], qa[ks][2], qa[ks][3],
                             __float_as_uint(b0), __float_as_uint(b1));
                }
            }
        }

        // --- STS next V tile (transposed) while MMA results settle ---
        if (pre) {
            float* dst = sVt[buf ^ 1];
            #pragma unroll
            for (int i = 0; i < 4; i++) {
                dst[(vcb + 4 * i + 0) * FA_P + vrow] = to_tf32(vr[i].x);
                dst[(vcb + 4 * i + 1) * FA_P + vrow] = to_tf32(vr[i].y);
                dst[(vcb + 4 * i + 2) * FA_P + vrow] = to_tf32(vr[i].z);
                dst[(vcb + 4 * i + 3) * FA_P + vrow] = to_tf32(vr[i].w);
            }
        }

        // --- online softmax in registers ---
        float mt0 = -1e30f, mt1 = -1e30f;
        #pragma unroll
        for (int j = 0; j < 8; j++) {
            mt0 = fmaxf(mt0, fmaxf(s[j][0], s[j][1]));
            mt1 = fmaxf(mt1, fmaxf(s[j][2], s[j][3]));
        }
        mt0 = fmaxf(mt0, __shfl_xor_sync(fm, mt0, 1));
        mt0 = fmaxf(mt0, __shfl_xor_sync(fm, mt0, 2));
        mt1 = fmaxf(mt1, __shfl_xor_sync(fm, mt1, 1));
        mt1 = fmaxf(mt1, __shfl_xor_sync(fm, mt1, 2));
        const float mn0 = fmaxf(m0, mt0);
        const float mn1 = fmaxf(m1, mt1);
        const float al0 = __expf(m0 - mn0);
        const float al1 = __expf(m1 - mn1);
        m0 = mn0; m1 = mn1;
        float rs0 = 0.f, rs1 = 0.f;
        #pragma unroll
        for (int j = 0; j < 8; j++) {
            s[j][0] = __expf(s[j][0] - mn0); rs0 += s[j][0];
            s[j][1] = __expf(s[j][1] - mn0); rs0 += s[j][1];
            s[j][2] = __expf(s[j][2] - mn1); rs1 += s[j][2];
            s[j][3] = __expf(s[j][3] - mn1); rs1 += s[j][3];
        }
        rs0 += __shfl_xor_sync(fm, rs0, 1);
        rs0 += __shfl_xor_sync(fm, rs0, 2);
        rs1 += __shfl_xor_sync(fm, rs1, 1);
        rs1 += __shfl_xor_sync(fm, rs1, 2);
        l0 = l0 * al0 + rs0;
        l1 = l1 * al1 + rs1;
        #pragma unroll
        for (int j = 0; j < 8; j++) {
            acc_o[j][0] *= al0; acc_o[j][1] *= al0;
            acc_o[j][2] *= al1; acc_o[j][3] *= al1;
        }

        // --- P @ V (C-layout -> A-layout via quad shuffles) ---
        {
            const float* vt = sVt[buf];
            const bool odd = tq & 1;
            #pragma unroll
            for (int ks = 0; ks < 8; ks++) {
                const float e00 = __shfl_sync(fm, s[ks][0], src0);
                const float e01 = __shfl_sync(fm, s[ks][1], src0);
                const float e10 = __shfl_sync(fm, s[ks][2], src0);
                const float e11 = __shfl_sync(fm, s[ks][3], src0);
                const float e20 = __shfl_sync(fm, s[ks][0], src2);
                const float e21 = __shfl_sync(fm, s[ks][1], src2);
                const float e30 = __shfl_sync(fm, s[ks][2], src2);
                const float e31 = __shfl_sync(fm, s[ks][3], src2);
                const uint32_t pa0 = __float_as_uint(to_tf32(odd ? e01 : e00));
                const uint32_t pa1 = __float_as_uint(to_tf32(odd ? e11 : e10));
                const uint32_t pa2 = __float_as_uint(to_tf32(odd ? e21 : e20));
                const uint32_t pa3 = __float_as_uint(to_tf32(odd ? e31 : e30));
                #pragma unroll
                for (int jd = 0; jd < 8; jd++) {
                    const float b0 = vt[(8 * jd + g) * FA_P + 8 * ks + tq];
                    const float b1 = vt[(8 * jd + g) * FA_P + 8 * ks + tq + 4];
                    mma_tf32(acc_o[jd], pa0, pa1, pa2, pa3,
                             __float_as_uint(b0), __float_as_uint(b1));
                }
            }
        }
    }

    // --- epilogue: normalize and store ---
    const float inv0 = 1.0f / l0;
    const float inv1 = 1.0f / l1;
    const size_t row0 = (size_t)(b * NT + q0 + warp * 16 + g);
    float* o0 = O + row0 * ND + h * NDH;
    float* o1 = o0 + (size_t)8 * ND;
    #pragma unroll
    for (int jd = 0; jd < 8; jd++) {
        *(float2*)(o0 + 8 * jd + 2 * tq) =
            make_float2(acc_o[jd][0] * inv0, acc_o[jd][1] * inv0);
        *(float2*)(o1 + 8 * jd + 2 * tq) =
            make_float2(acc_o[jd][2] * inv1, acc_o[jd][3] * inv1);
    }
}

// ---------------------------------------------------------------------------
extern "C" void kernel_launch(void* const* d_in, const int* in_sizes, int n_in,
                              void* d_out, int out_size)
{
    const float* x  = (const float*)d_in[0];
    const float* Wq = (const float*)d_in[1];
    const float* Wk = (const float*)d_in[2];
    const float* Wv = (const float*)d_in[3];
    const float* Wo = (const float*)d_in[4];
    float* out = (float*)d_out;

    float *Qp, *Kp, *Vp, *Ap;
    cudaGetSymbolAddress((void**)&Qp, g_Q);
    cudaGetSymbolAddress((void**)&Kp, g_K);
    cudaGetSymbolAddress((void**)&Vp, g_V);
    cudaGetSymbolAddress((void**)&Ap, g_A);

    cudaFuncSetAttribute(flash_mma,
                         cudaFuncAttributeMaxDynamicSharedMemorySize, FA2_SMEM);

    dim3 gq(ND / 128, NTOK / 128);     // (16, 32)
    dim3 gkv(NDKV / 128, NTOK / 128);  // (4, 32)

    gemm_tf32<<<gq, 256>>>(x, Wq, Qp, NTOK, ND, ND);
    gemm_tf32<<<gkv, 256>>>(x, Wk, Kp, NTOK, NDKV, ND);
    gemm_tf32<<<gkv, 256>>>(x, Wv, Vp, NTOK, NDKV, ND);

    flash_mma<<<dim3(NT / 128, NB * NHQ), 256, FA2_SMEM>>>(Qp, Kp, Vp, Ap);

    gemm_tf32<<<gq, 256>>>(Ap, Wo, out, NTOK, ND, ND);
}